// round 4
// baseline (speedup 1.0000x reference)
#include <cuda_runtime.h>

#define N    4096
#define IT   30
#define G    128            // persistent blocks, co-resident (1/SM)
#define TPB  1024
#define NF4  (N / 4)        // 1024: float4 slots per row / 4-row groups
#define TOTF4 ((size_t)N * N / 4)

// Scratch (__device__ globals: allocation-free rule)
static __device__ float g_B0[(size_t)N * N];   // (mean+std*eps)*log2(e)/TAU
static __device__ float g_r[N];
static __device__ float g_c[N];
static __device__ float g_part[(size_t)G * N]; // [block][col] column partials
static __device__ unsigned g_arrive;           // barrier counter (0-init)
static __device__ unsigned g_gen;              // barrier generation

__device__ __forceinline__ float ex2(float x) {
    float y; asm("ex2.approx.ftz.f32 %0, %1;" : "=f"(y) : "f"(x)); return y;
}
__device__ __forceinline__ float lg2(float x) {
    float y; asm("lg2.approx.f32 %0, %1;" : "=f"(y) : "f"(x)); return y;
}
__device__ __forceinline__ float rcp(float x) {
    float y; asm("rcp.approx.ftz.f32 %0, %1;" : "=f"(y) : "f"(x)); return y;
}

// Grid-wide barrier (all G blocks co-resident by construction).
__device__ __forceinline__ void grid_bar() {
    __syncthreads();
    if (threadIdx.x == 0) {
        __threadfence();
        unsigned gen = *((volatile unsigned*)&g_gen);
        if (atomicAdd(&g_arrive, 1u) == (unsigned)G - 1u) {
            g_arrive = 0u;
            __threadfence();
            *((volatile unsigned*)&g_gen) = gen + 1u;
        } else {
            while (*((volatile unsigned*)&g_gen) == gen) { }
        }
        __threadfence();
    }
    __syncthreads();
}

__global__ void __launch_bounds__(TPB, 1)
sinkhorn_persistent(const float* __restrict__ eps,
                    const float* __restrict__ mean,
                    const float* __restrict__ stdv,
                    float* __restrict__ out) {
    const int b    = blockIdx.x;
    const int t    = threadIdx.x;          // 0..1023 : owns cols 4t..4t+3
    const int lane = t & 31;
    const int warp = t >> 5;               // 0..31
    const unsigned gtid = b * TPB + t;

    // ---------------- Phase 0: setup -------------------------------------
    {
        const float SCALE = 0.72134752044448170368f;  // log2(e)/TAU, TAU=2
        const float4* e4 = (const float4*)eps;
        const float4* m4 = (const float4*)mean;
        const float4* s4 = (const float4*)stdv;
        float4* b4 = (float4*)g_B0;
        for (size_t i = gtid; i < TOTF4; i += (size_t)G * TPB) {
            float4 e = e4[i], m = m4[i], s = s4[i];
            float4 o;
            o.x = (m.x + s.x * e.x) * SCALE;
            o.y = (m.y + s.y * e.y) * SCALE;
            o.z = (m.z + s.z * e.z) * SCALE;
            o.w = (m.w + s.w * e.w) * SCALE;
            b4[i] = o;
        }
        float4 z = make_float4(0.f, 0.f, 0.f, 0.f);
        if (gtid < 1024)      ((float4*)g_c)[gtid] = z;
        else if (gtid < 2048) ((float4*)g_r)[gtid - 1024] = z;
    }
    grid_bar();

    __shared__ float4 red[2][32];          // double-buffered warp partials

    for (int it = 0; it < IT; it++) {
        const float4 cA = __ldcg(((const float4*)g_c) + t);
        float acc0 = 0.f, acc1 = 0.f, acc2 = 0.f, acc3 = 0.f;

        // -------- fused row + column sweep: 4 rows/group, 8 groups -------
        #pragma unroll 1
        for (int g = b, buf = 0; g < NF4; g += G, buf ^= 1) {
            const int i0 = g * 4;
            // issue all loads up front (MLP)
            const float rp0 = __ldcg(g_r + i0 + 0);
            const float rp1 = __ldcg(g_r + i0 + 1);
            const float rp2 = __ldcg(g_r + i0 + 2);
            const float rp3 = __ldcg(g_r + i0 + 3);
            const float4 b0 = __ldcg((const float4*)(g_B0 + (size_t)(i0 + 0) * N) + t);
            const float4 b1 = __ldcg((const float4*)(g_B0 + (size_t)(i0 + 1) * N) + t);
            const float4 b2 = __ldcg((const float4*)(g_B0 + (size_t)(i0 + 2) * N) + t);
            const float4 b3 = __ldcg((const float4*)(g_B0 + (size_t)(i0 + 3) * N) + t);

            float e00 = ex2(b0.x - cA.x - rp0), e01 = ex2(b0.y - cA.y - rp0),
                  e02 = ex2(b0.z - cA.z - rp0), e03 = ex2(b0.w - cA.w - rp0);
            float e10 = ex2(b1.x - cA.x - rp1), e11 = ex2(b1.y - cA.y - rp1),
                  e12 = ex2(b1.z - cA.z - rp1), e13 = ex2(b1.w - cA.w - rp1);
            float e20 = ex2(b2.x - cA.x - rp2), e21 = ex2(b2.y - cA.y - rp2),
                  e22 = ex2(b2.z - cA.z - rp2), e23 = ex2(b2.w - cA.w - rp2);
            float e30 = ex2(b3.x - cA.x - rp3), e31 = ex2(b3.y - cA.y - rp3),
                  e32 = ex2(b3.z - cA.z - rp3), e33 = ex2(b3.w - cA.w - rp3);

            float p0 = (e00 + e01) + (e02 + e03);
            float p1 = (e10 + e11) + (e12 + e13);
            float p2 = (e20 + e21) + (e22 + e23);
            float p3 = (e30 + e31) + (e32 + e33);

            // stage 1: warp butterfly
            #pragma unroll
            for (int o = 16; o > 0; o >>= 1) {
                p0 += __shfl_xor_sync(0xffffffffu, p0, o);
                p1 += __shfl_xor_sync(0xffffffffu, p1, o);
                p2 += __shfl_xor_sync(0xffffffffu, p2, o);
                p3 += __shfl_xor_sync(0xffffffffu, p3, o);
            }
            if (lane == 0) red[buf][warp] = make_float4(p0, p1, p2, p3);
            __syncthreads();                       // only barrier per group

            // stage 2: every warp redundantly reduces the 32 partials
            float4 q = red[buf][lane];
            #pragma unroll
            for (int o = 16; o > 0; o >>= 1) {
                q.x += __shfl_xor_sync(0xffffffffu, q.x, o);
                q.y += __shfl_xor_sync(0xffffffffu, q.y, o);
                q.z += __shfl_xor_sync(0xffffffffu, q.z, o);
                q.w += __shfl_xor_sync(0xffffffffu, q.w, o);
            }

            if (t == 0) {                          // r_new = r_prev + log2 S
                g_r[i0 + 0] = rp0 + lg2(q.x);
                g_r[i0 + 1] = rp1 + lg2(q.y);
                g_r[i0 + 2] = rp2 + lg2(q.z);
                g_r[i0 + 3] = rp3 + lg2(q.w);
            }

            // column contribution: 2^(B0-c_prev-r_new) = e/S   (free)
            const float s0 = rcp(q.x), s1 = rcp(q.y), s2 = rcp(q.z), s3 = rcp(q.w);
            acc0 += e00 * s0; acc1 += e01 * s0; acc2 += e02 * s0; acc3 += e03 * s0;
            acc0 += e10 * s1; acc1 += e11 * s1; acc2 += e12 * s1; acc3 += e13 * s1;
            acc0 += e20 * s2; acc1 += e21 * s2; acc2 += e22 * s2; acc3 += e23 * s2;
            acc0 += e30 * s3; acc1 += e31 * s3; acc2 += e32 * s3; acc3 += e33 * s3;
        }

        // write column partials (coalesced [block][col])
        ((float4*)(g_part + (size_t)b * N))[t] = make_float4(acc0, acc1, acc2, acc3);
        grid_bar();

        // combine: warp 0 of each block owns 32 columns
        if (t < 32) {
            const int col = b * 32 + t;
            float sum = 0.f;
            #pragma unroll 8
            for (int k = 0; k < G; k++)
                sum += __ldcg(g_part + (size_t)k * N + col);
            g_c[col] = __ldcg(g_c + col) + lg2(sum);
        }
        grid_bar();
    }

    // ---------------- Final: out = 2^(B0 - r(i) - c(j)) ------------------
    {
        const float4* b4 = (const float4*)g_B0;
        float4* o4 = (float4*)out;
        for (size_t i = gtid; i < TOTF4; i += (size_t)G * TPB) {
            int row = (int)(i >> 10);
            int cf  = (int)(i & 1023);
            float rv  = __ldcg(g_r + row);
            float4 cv = __ldcg(((const float4*)g_c) + cf);
            float4 bb = b4[i];
            float4 o;
            o.x = ex2(bb.x - rv - cv.x);
            o.y = ex2(bb.y - rv - cv.y);
            o.z = ex2(bb.z - rv - cv.z);
            o.w = ex2(bb.w - rv - cv.w);
            o4[i] = o;
        }
    }
}

extern "C" void kernel_launch(void* const* d_in, const int* in_sizes, int n_in,
                              void* d_out, int out_size) {
    const float* eps  = (const float*)d_in[0];
    const float* mean = (const float*)d_in[1];
    const float* stdv = (const float*)d_in[2];
    sinkhorn_persistent<<<G, TPB>>>(eps, mean, stdv, (float*)d_out);
}

// round 5
// speedup vs baseline: 2.3108x; 2.3108x over previous
#include <cuda_runtime.h>

#define N     4096
#define IT    30
#define G     128            // persistent blocks, 1/SM, co-resident
#define TPB   1024           // 32 warps: warp-per-row in row phase
#define NF4   (N / 4)        // 1024 float4 slots per row
#define TOTF4 ((size_t)N * N / 4)

// Scratch (__device__ globals: allocation-free rule)
static __device__ float g_B0[(size_t)N * N];   // (mean+std*eps)*log2(e)/TAU
static __device__ float g_r[N];
static __device__ float g_c[N];
static __device__ float g_part[(size_t)G * N]; // [block][col] partial col sums
static __device__ unsigned g_arrive;           // barrier counter (0-init)
static __device__ unsigned g_gen;              // barrier generation (monotonic)

__device__ __forceinline__ float ex2(float x) {
    float y; asm("ex2.approx.ftz.f32 %0, %1;" : "=f"(y) : "f"(x)); return y;
}
__device__ __forceinline__ float lg2(float x) {
    float y; asm("lg2.approx.f32 %0, %1;" : "=f"(y) : "f"(x)); return y;
}

// Grid-wide barrier (all G blocks co-resident by construction).
__device__ __forceinline__ void grid_bar() {
    __syncthreads();
    if (threadIdx.x == 0) {
        __threadfence();
        unsigned gen = *((volatile unsigned*)&g_gen);
        if (atomicAdd(&g_arrive, 1u) == (unsigned)G - 1u) {
            g_arrive = 0u;
            __threadfence();
            *((volatile unsigned*)&g_gen) = gen + 1u;
        } else {
            while (*((volatile unsigned*)&g_gen) == gen) { }
        }
        __threadfence();
    }
    __syncthreads();
}

__global__ void __launch_bounds__(TPB, 1)
sinkhorn_persistent(const float* __restrict__ eps,
                    const float* __restrict__ mean,
                    const float* __restrict__ stdv,
                    float* __restrict__ out) {
    const int b    = blockIdx.x;
    const int t    = threadIdx.x;
    const int lane = t & 31;
    const int warp = t >> 5;               // 0..31
    const unsigned gtid = b * TPB + t;

    __shared__ float sC[N];                // staged c (16 KB)
    __shared__ float sPart[32][33];        // combine scratch (padded)

    // ---------------- Phase 0: setup -------------------------------------
    {
        const float SCALE = 0.72134752044448170368f;  // log2(e)/TAU, TAU=2
        const float4* e4 = (const float4*)eps;
        const float4* m4 = (const float4*)mean;
        const float4* s4 = (const float4*)stdv;
        float4* b4 = (float4*)g_B0;
        for (size_t i = gtid; i < TOTF4; i += (size_t)G * TPB) {
            float4 e = e4[i], m = m4[i], s = s4[i];
            float4 o;
            o.x = (m.x + s.x * e.x) * SCALE;
            o.y = (m.y + s.y * e.y) * SCALE;
            o.z = (m.z + s.z * e.z) * SCALE;
            o.w = (m.w + s.w * e.w) * SCALE;
            b4[i] = o;
        }
        float4 z = make_float4(0.f, 0.f, 0.f, 0.f);
        if (gtid < 1024)      ((float4*)g_c)[gtid] = z;
        else if (gtid < 2048) ((float4*)g_r)[gtid - 1024] = z;
    }
    grid_bar();

    const int i0 = b * 32;                 // this block's 32-row stripe

    for (int it = 0; it < IT; it++) {
        // stage c into shared (c is cross-block mutable -> ldcg)
        {
            float4 cv = __ldcg(((const float4*)g_c) + t);
            ((float4*)sC)[t] = cv;
        }
        __syncthreads();

        // ---------- row phase: warp w owns row i0 + w, fully independent --
        {
            const int row = i0 + warp;
            const float4* __restrict__ rowp =
                (const float4*)(g_B0 + (size_t)row * N);
            const float rp = g_r[row];     // own block wrote it -> L1 safe
            float s = 0.f;
            #pragma unroll 4
            for (int k = 0; k < 32; k++) {
                const int slot = lane + 32 * k;
                float4 bb = rowp[slot];
                float4 cc = ((const float4*)sC)[slot];
                s += ex2((bb.x - cc.x) - rp);
                s += ex2((bb.y - cc.y) - rp);
                s += ex2((bb.z - cc.z) - rp);
                s += ex2((bb.w - cc.w) - rp);
            }
            #pragma unroll
            for (int o = 16; o > 0; o >>= 1)
                s += __shfl_xor_sync(0xffffffffu, s, o);
            if (lane == 0) g_r[row] = rp + lg2(s);
        }
        __syncthreads();                   // r stripe visible (CTA scope)

        // ---------- col phase: thread owns float4 col slot t --------------
        {
            const float4 cA = ((const float4*)sC)[t];
            float4 acc = make_float4(0.f, 0.f, 0.f, 0.f);
            #pragma unroll 4
            for (int i = 0; i < 32; i++) {
                const int row = i0 + i;
                float4 bb = ((const float4*)(g_B0 + (size_t)row * N))[t];
                float rv = g_r[row];       // own block's write -> L1 safe
                acc.x += ex2((bb.x - cA.x) - rv);
                acc.y += ex2((bb.y - cA.y) - rv);
                acc.z += ex2((bb.z - cA.z) - rv);
                acc.w += ex2((bb.w - cA.w) - rv);
            }
            ((float4*)(g_part + (size_t)b * N))[t] = acc;
        }
        grid_bar();                        // all partials visible

        // ---------- combine: block b folds its own 32 columns -------------
        {
            const int kk = warp;           // partial-chunk group 0..31
            const int cl = lane;           // local column 0..31
            const int col = b * 32 + cl;
            float s4 = 0.f;
            #pragma unroll
            for (int q = 0; q < 4; q++)
                s4 += __ldcg(g_part + (size_t)(kk * 4 + q) * N + col);
            sPart[kk][cl] = s4;
            __syncthreads();
            if (t < 32) {
                float s = 0.f;
                #pragma unroll
                for (int k = 0; k < 32; k++) s += sPart[k][t];
                const int j = b * 32 + t;
                g_c[j] = __ldcg(g_c + j) + lg2(s);
            }
        }
        grid_bar();                        // c visible to all
    }

    // ---------------- Final: out = 2^(B0 - r(i) - c(j)) ------------------
    {
        const float4* b4 = (const float4*)g_B0;
        float4* o4 = (float4*)out;
        for (size_t i = gtid; i < TOTF4; i += (size_t)G * TPB) {
            int row = (int)(i >> 10);
            int cf  = (int)(i & 1023);
            float rv  = __ldcg(g_r + row);
            float4 cv = __ldcg(((const float4*)g_c) + cf);
            float4 bb = b4[i];
            float4 o;
            o.x = ex2((bb.x - cv.x) - rv);
            o.y = ex2((bb.y - cv.y) - rv);
            o.z = ex2((bb.z - cv.z) - rv);
            o.w = ex2((bb.w - cv.w) - rv);
            o4[i] = o;
        }
    }
}

extern "C" void kernel_launch(void* const* d_in, const int* in_sizes, int n_in,
                              void* d_out, int out_size) {
    const float* eps  = (const float*)d_in[0];
    const float* mean = (const float*)d_in[1];
    const float* stdv = (const float*)d_in[2];
    sinkhorn_persistent<<<G, TPB>>>(eps, mean, stdv, (float*)d_out);
}